// round 10
// baseline (speedup 1.0000x reference)
#include <cuda_runtime.h>
#include <cuda_fp16.h>
#include <cstdint>

// Problem shape (fixed):
//   x:      [8192, 4096] f32 (A, row-major)      d_in[0]
//   weight: [4096, 4096] f32 (W, row-major)      d_in[1]
//   bias:   [4096] f32                           d_in[2]
//   sw:     [262144] f32                         d_in[3]
//   idx:    [2, 262144] i32 (rows, cols)         d_in[4]
//   out = x @ (W + scatter)^T + bias   [8192, 4096] f32
//
// R10: 8 warps/CTA (256 thr), warp tile 64x32, still 2 CTAs/SM (96KB smem).
// -> 4 warps per SMSP from two independent barrier domains; fp16 m16n8k16
//    (f32 acc), BK=64, 3-stage cp.async, ldmatrix.x4, XOR-swizzled smem.

#define M_DIM 8192
#define N_DIM 4096
#define K_DIM 4096

#define BM 128
#define BN 128
#define BK 64                    // halves per k-tile (128B rows)
#define STAGES 3
#define NKT (K_DIM / BK)         // 64
#define NTHREADS 256

#define A_STAGE_BYTES (BM * BK * 2)     // 16384
#define B_STAGE_BYTES (BN * BK * 2)     // 16384
#define SMEM_TOTAL (STAGES * (A_STAGE_BYTES + B_STAGE_BYTES))   // 98304

// Device scratch (allocation-free): fp16 copies. Touched ONLY from device code.
__device__ __half g_wt[(size_t)N_DIM * K_DIM];
__device__ __half g_x[(size_t)M_DIM * K_DIM];

// ---------------------------------------------------------------------------
// helpers
// ---------------------------------------------------------------------------
__device__ __forceinline__ uint32_t smem_u32(const void* p) {
    uint32_t a;
    asm("{ .reg .u64 t; cvta.to.shared.u64 t, %1; cvt.u32.u64 %0, t; }"
        : "=r"(a) : "l"(p));
    return a;
}

#define CP_ASYNC16(dst, src) \
    asm volatile("cp.async.cg.shared.global [%0], [%1], 16;" :: "r"(dst), "l"(src))
#define CP_COMMIT() asm volatile("cp.async.commit_group;" ::: "memory")
#define CP_WAIT1()  asm volatile("cp.async.wait_group 1;" ::: "memory")

#define LDSM_X4(r0, r1, r2, r3, addr)                                   \
    asm volatile("ldmatrix.sync.aligned.m8n8.x4.shared.b16 "            \
                 "{%0,%1,%2,%3}, [%4];"                                 \
                 : "=r"(r0), "=r"(r1), "=r"(r2), "=r"(r3) : "r"(addr))

__device__ __forceinline__ void mma_f16(float& c0, float& c1, float& c2, float& c3,
                                        uint32_t a0, uint32_t a1, uint32_t a2, uint32_t a3,
                                        uint32_t b0, uint32_t b1) {
    asm volatile(
        "mma.sync.aligned.m16n8k16.row.col.f32.f16.f16.f32 "
        "{%0,%1,%2,%3}, {%4,%5,%6,%7}, {%8,%9}, {%0,%1,%2,%3};"
        : "+f"(c0), "+f"(c1), "+f"(c2), "+f"(c3)
        : "r"(a0), "r"(a1), "r"(a2), "r"(a3), "r"(b0), "r"(b1));
}

// ---------------------------------------------------------------------------
// Prologue: f32 -> fp16 (RNE) converts + half scatter-add
// ---------------------------------------------------------------------------
__device__ __forceinline__ void cvt8(const float4* __restrict__ src4,
                                     uint4* __restrict__ dst, size_t i) {
    float4 a = src4[i * 2 + 0];
    float4 b = src4[i * 2 + 1];
    __half2 h0 = __floats2half2_rn(a.x, a.y);
    __half2 h1 = __floats2half2_rn(a.z, a.w);
    __half2 h2 = __floats2half2_rn(b.x, b.y);
    __half2 h3 = __floats2half2_rn(b.z, b.w);
    uint4 o;
    o.x = *reinterpret_cast<uint32_t*>(&h0);
    o.y = *reinterpret_cast<uint32_t*>(&h1);
    o.z = *reinterpret_cast<uint32_t*>(&h2);
    o.w = *reinterpret_cast<uint32_t*>(&h3);
    dst[i] = o;
}

__global__ void convert_w_kernel(const float4* __restrict__ w) {
    size_t i = (size_t)blockIdx.x * blockDim.x + threadIdx.x;
    cvt8(w, reinterpret_cast<uint4*>(g_wt), i);
}

__global__ void convert_x_kernel(const float4* __restrict__ x) {
    size_t i = (size_t)blockIdx.x * blockDim.x + threadIdx.x;
    cvt8(x, reinterpret_cast<uint4*>(g_x), i);
}

__global__ void scatter_add_kernel(const float* __restrict__ sw,
                                   const int* __restrict__ rows,
                                   const int* __restrict__ cols, int nnz) {
    int i = blockIdx.x * blockDim.x + threadIdx.x;
    if (i < nnz)
        atomicAdd(&g_wt[(size_t)rows[i] * K_DIM + cols[i]], __float2half(sw[i]));
}

// ---------------------------------------------------------------------------
// GEMM: C[M,N] = A @ W'^T + bias
//   mma.sync m16n8k16 f16 (f32 acc), CTA 128x128, 8 warps 2x4 (64x32 each),
//   BK=64, 3-stage cp.async pipeline, ldmatrix.x4 fragments, 2 CTAs/SM.
// ---------------------------------------------------------------------------
__global__ __launch_bounds__(NTHREADS, 2)
void gemm_f16_kernel(const float* __restrict__ bias,
                     float* __restrict__ C) {
    extern __shared__ char smem[];
    const uint32_t sb = smem_u32(smem);

    const int tid  = threadIdx.x;
    const int wid  = tid >> 5;
    const int lane = tid & 31;
    const int lr   = lane >> 2;     // row-in-fragment group
    const int lq   = lane & 3;      // thread-in-group

    const int warpM = (wid >> 2) * 64;   // 0 or 64
    const int warpN = (wid & 3) * 32;    // 0,32,64,96

    const int bm = blockIdx.y * BM;
    const int bn = blockIdx.x * BN;

    const __half* Ab = g_x + (size_t)bm * K_DIM;
    const __half* Bb = g_wt + (size_t)bn * K_DIM;

    // ldmatrix lane->address mapping:
    // A x4 = {rows r..r+7 @c, rows+8 @c, rows @c+1, rows+8 @c+1}
    const int aRow  = warpM + (lane & 15);        // + mt*16
    const int aCSel = lane >> 4;                  // 0 or 1
    // B x4 = {n..n+7 @c, n..n+7 @c+1, n+8..15 @c, n+8..15 @c+1}
    const int bRow  = warpN + (lane & 7) + ((lane >> 4) << 3);  // + ntp*16
    const int bCSel = (lane >> 3) & 1;            // 0 or 1

    // tile loader: 16B chunk (row r, chunk c 0..7) -> smem r*128 + ((c^(r&7))*16)
#define LOAD_TILE(t, s)                                                         \
    {                                                                           \
        const uint32_t ab = sb + (s) * A_STAGE_BYTES;                           \
        _Pragma("unroll")                                                       \
        for (int j = 0; j < 4; j++) {                                           \
            int i = tid + j * NTHREADS;          /* 0..1023 */                  \
            int r = i >> 3, c = i & 7;                                          \
            uint32_t dst = ab + (uint32_t)(r * 128 + ((c ^ (r & 7)) << 4));     \
            CP_ASYNC16(dst, Ab + (size_t)r * K_DIM + (t) * BK + c * 8);         \
        }                                                                       \
        const uint32_t bb = sb + STAGES * A_STAGE_BYTES + (s) * B_STAGE_BYTES;  \
        _Pragma("unroll")                                                       \
        for (int j = 0; j < 4; j++) {                                           \
            int i = tid + j * NTHREADS;          /* 0..1023 */                  \
            int r = i >> 3, c = i & 7;                                          \
            uint32_t dst = bb + (uint32_t)(r * 128 + ((c ^ (r & 7)) << 4));     \
            CP_ASYNC16(dst, Bb + (size_t)r * K_DIM + (t) * BK + c * 8);         \
        }                                                                       \
    }

    // prologue: tiles 0,1 into stages 0,1
    LOAD_TILE(0, 0);
    CP_COMMIT();
    LOAD_TILE(1, 1);
    CP_COMMIT();

    float acc[4][4][4];
#pragma unroll
    for (int i = 0; i < 4; i++)
#pragma unroll
        for (int j = 0; j < 4; j++)
#pragma unroll
            for (int q = 0; q < 4; q++) acc[i][j][q] = 0.0f;

    int s = 0;            // stage of tile t
    int sp = 2;           // stage for prefetch (t+2)
    for (int t = 0; t < NKT; t++) {
        CP_WAIT1();          // tile t resident (<=1 younger group outstanding)
        __syncthreads();     // cross-thread visibility + retiring-stage WAR

        if (t + 2 < NKT) {
            LOAD_TILE(t + 2, sp);
        }
        CP_COMMIT();         // empty groups in tail keep wait-count semantics

        const uint32_t abase = sb + s * A_STAGE_BYTES;
        const uint32_t bbase = sb + STAGES * A_STAGE_BYTES + s * B_STAGE_BYTES;

        // 4 kk-steps of K=16 halves (chunk pair 2kk, 2kk+1)
#pragma unroll
        for (int kk = 0; kk < 4; kk++) {
            uint32_t ua[4][4], ub[2][4];
#pragma unroll
            for (int mt = 0; mt < 4; mt++) {
                const int r = aRow + mt * 16;
                const int c = 2 * kk + aCSel;
                const uint32_t addr =
                    abase + (uint32_t)(r * 128 + ((c ^ (r & 7)) << 4));
                LDSM_X4(ua[mt][0], ua[mt][1], ua[mt][2], ua[mt][3], addr);
            }
#pragma unroll
            for (int ntp = 0; ntp < 2; ntp++) {
                const int n = bRow + ntp * 16;
                const int c = 2 * kk + bCSel;
                const uint32_t addr =
                    bbase + (uint32_t)(n * 128 + ((c ^ (n & 7)) << 4));
                LDSM_X4(ub[ntp][0], ub[ntp][1], ub[ntp][2], ub[ntp][3], addr);
            }
#pragma unroll
            for (int mt = 0; mt < 4; mt++)
#pragma unroll
                for (int nt = 0; nt < 4; nt++) {
                    const uint32_t b0 = (nt & 1) ? ub[nt >> 1][2] : ub[nt >> 1][0];
                    const uint32_t b1 = (nt & 1) ? ub[nt >> 1][3] : ub[nt >> 1][1];
                    mma_f16(acc[mt][nt][0], acc[mt][nt][1],
                            acc[mt][nt][2], acc[mt][nt][3],
                            ua[mt][0], ua[mt][1], ua[mt][2], ua[mt][3],
                            b0, b1);
                }
        }

        s = (s == 2) ? 0 : s + 1;
        sp = (sp == 2) ? 0 : sp + 1;
    }

    // Epilogue: bias + store (float2 per fragment row)
#pragma unroll
    for (int nt = 0; nt < 4; nt++) {
        const int col = bn + warpN + nt * 8 + lq * 2;
        const float bv0 = bias[col];
        const float bv1 = bias[col + 1];
#pragma unroll
        for (int mt = 0; mt < 4; mt++) {
            const int r0 = bm + warpM + mt * 16 + lr;
            float2 v0, v1;
            v0.x = acc[mt][nt][0] + bv0;
            v0.y = acc[mt][nt][1] + bv1;
            v1.x = acc[mt][nt][2] + bv0;
            v1.y = acc[mt][nt][3] + bv1;
            *reinterpret_cast<float2*>(&C[(size_t)r0 * N_DIM + col]) = v0;
            *reinterpret_cast<float2*>(&C[(size_t)(r0 + 8) * N_DIM + col]) = v1;
        }
    }
}

// ---------------------------------------------------------------------------
// Launch
// ---------------------------------------------------------------------------
extern "C" void kernel_launch(void* const* d_in, const int* in_sizes, int n_in,
                              void* d_out, int out_size) {
    const float* x    = (const float*)d_in[0];
    const float* w    = (const float*)d_in[1];
    const float* bias = (const float*)d_in[2];
    const float* sw   = (const float*)d_in[3];
    const int*   idx  = (const int*)d_in[4];
    float*       out  = (float*)d_out;
    const int nnz = in_sizes[3];

    // 1) W' = half(W)
    convert_w_kernel<<<(N_DIM * K_DIM / 8) / 256, 256>>>(
        reinterpret_cast<const float4*>(w));
    // 2) W' += scatter(sw)  (half atomics, RNE per add)
    scatter_add_kernel<<<(nnz + 255) / 256, 256>>>(sw, idx, idx + nnz, nnz);
    // 3) x' = half(x)
    convert_x_kernel<<<(int)(((size_t)M_DIM * K_DIM / 8) / 256), 256>>>(
        reinterpret_cast<const float4*>(x));

    // 4) GEMM
    cudaFuncSetAttribute(gemm_f16_kernel,
                         cudaFuncAttributeMaxDynamicSharedMemorySize, SMEM_TOTAL);
    dim3 grid(N_DIM / BN, M_DIM / BM);   // (32, 64)
    gemm_f16_kernel<<<grid, NTHREADS, SMEM_TOTAL>>>(bias, out);
}

// round 11
// speedup vs baseline: 1.1212x; 1.1212x over previous
#include <cuda_runtime.h>
#include <cuda_fp16.h>
#include <cstdint>

// Problem shape (fixed):
//   x:      [8192, 4096] f32 (A, row-major)      d_in[0]
//   weight: [4096, 4096] f32 (W, row-major)      d_in[1]
//   bias:   [4096] f32                           d_in[2]
//   sw:     [262144] f32                         d_in[3]
//   idx:    [2, 262144] i32 (rows, cols)         d_in[4]
//   out = x @ (W + scatter)^T + bias   [8192, 4096] f32
//
// R11: R9's shape (fp16 m16n8k16, CTA 128x128, 4 warps of 64x64, BK=64,
// 3 stages, 2 CTAs/SM) but the per-k-tile __syncthreads is replaced by an
// mbarrier producer/consumer pipeline (full = cp.async.mbarrier.arrive.noinc,
// empty = mbarrier.arrive). Warps decouple: no lockstep rendezvous per tile.

#define M_DIM 8192
#define N_DIM 4096
#define K_DIM 4096

#define BM 128
#define BN 128
#define BK 64                    // halves per k-tile (128B rows)
#define STAGES 3
#define NKT (K_DIM / BK)         // 64
#define NTHREADS 128

#define A_STAGE_BYTES (BM * BK * 2)     // 16384
#define B_STAGE_BYTES (BN * BK * 2)     // 16384
#define DATA_BYTES (STAGES * (A_STAGE_BYTES + B_STAGE_BYTES))   // 98304
#define MB_OFF DATA_BYTES                 // full[s]=+s*16, empty[s]=+s*16+8
#define SMEM_TOTAL (DATA_BYTES + 64)

// Device scratch (allocation-free): fp16 copies. Touched ONLY from device code.
__device__ __half g_wt[(size_t)N_DIM * K_DIM];
__device__ __half g_x[(size_t)M_DIM * K_DIM];

// ---------------------------------------------------------------------------
// helpers
// ---------------------------------------------------------------------------
__device__ __forceinline__ uint32_t smem_u32(const void* p) {
    uint32_t a;
    asm("{ .reg .u64 t; cvta.to.shared.u64 t, %1; cvt.u32.u64 %0, t; }"
        : "=r"(a) : "l"(p));
    return a;
}

#define CP_ASYNC16(dst, src) \
    asm volatile("cp.async.cg.shared.global [%0], [%1], 16;" :: "r"(dst), "l"(src))

#define MBAR_INIT(a, n) \
    asm volatile("mbarrier.init.shared.b64 [%0], %1;" :: "r"(a), "r"((uint32_t)(n)) : "memory")
#define MBAR_ARRIVE(a) \
    asm volatile("mbarrier.arrive.shared.b64 _, [%0];" :: "r"(a) : "memory")
// arrive triggered when ALL prior cp.asyncs of this thread complete (.noinc:
// pending count pre-set by init, not incremented here)
#define CP_MBAR_ARRIVE(a) \
    asm volatile("cp.async.mbarrier.arrive.noinc.shared.b64 [%0];" :: "r"(a) : "memory")

#define MBAR_WAIT(a, ph) do {                                                    \
    uint32_t _m = (a), _p = (ph), _d;                                            \
    asm volatile("{ .reg .pred p; mbarrier.try_wait.parity.acquire.cta.shared::cta.b64 p, [%1], %2;" \
                 " selp.b32 %0, 1, 0, p; }" : "=r"(_d) : "r"(_m), "r"(_p) : "memory"); \
    if (!_d) {                                                                   \
        asm volatile("{ .reg .pred P1; WL_%=: mbarrier.try_wait.parity.acquire.cta.shared::cta.b64 P1, [%0], %1, 0x989680;" \
                     " @P1 bra.uni WD_%=; bra.uni WL_%=; WD_%=: }"               \
                     :: "r"(_m), "r"(_p) : "memory");                            \
    }                                                                            \
} while (0)

#define LDSM_X4(r0, r1, r2, r3, addr)                                   \
    asm volatile("ldmatrix.sync.aligned.m8n8.x4.shared.b16 "            \
                 "{%0,%1,%2,%3}, [%4];"                                 \
                 : "=r"(r0), "=r"(r1), "=r"(r2), "=r"(r3) : "r"(addr))

__device__ __forceinline__ void mma_f16(float& c0, float& c1, float& c2, float& c3,
                                        uint32_t a0, uint32_t a1, uint32_t a2, uint32_t a3,
                                        uint32_t b0, uint32_t b1) {
    asm volatile(
        "mma.sync.aligned.m16n8k16.row.col.f32.f16.f16.f32 "
        "{%0,%1,%2,%3}, {%4,%5,%6,%7}, {%8,%9}, {%0,%1,%2,%3};"
        : "+f"(c0), "+f"(c1), "+f"(c2), "+f"(c3)
        : "r"(a0), "r"(a1), "r"(a2), "r"(a3), "r"(b0), "r"(b1));
}

// ---------------------------------------------------------------------------
// Prologue: f32 -> fp16 (RNE) converts + half scatter-add
// ---------------------------------------------------------------------------
__device__ __forceinline__ void cvt8(const float4* __restrict__ src4,
                                     uint4* __restrict__ dst, size_t i) {
    float4 a = src4[i * 2 + 0];
    float4 b = src4[i * 2 + 1];
    __half2 h0 = __floats2half2_rn(a.x, a.y);
    __half2 h1 = __floats2half2_rn(a.z, a.w);
    __half2 h2 = __floats2half2_rn(b.x, b.y);
    __half2 h3 = __floats2half2_rn(b.z, b.w);
    uint4 o;
    o.x = *reinterpret_cast<uint32_t*>(&h0);
    o.y = *reinterpret_cast<uint32_t*>(&h1);
    o.z = *reinterpret_cast<uint32_t*>(&h2);
    o.w = *reinterpret_cast<uint32_t*>(&h3);
    dst[i] = o;
}

__global__ void convert_w_kernel(const float4* __restrict__ w) {
    size_t i = (size_t)blockIdx.x * blockDim.x + threadIdx.x;
    cvt8(w, reinterpret_cast<uint4*>(g_wt), i);
}

__global__ void convert_x_kernel(const float4* __restrict__ x) {
    size_t i = (size_t)blockIdx.x * blockDim.x + threadIdx.x;
    cvt8(x, reinterpret_cast<uint4*>(g_x), i);
}

__global__ void scatter_add_kernel(const float* __restrict__ sw,
                                   const int* __restrict__ rows,
                                   const int* __restrict__ cols, int nnz) {
    int i = blockIdx.x * blockDim.x + threadIdx.x;
    if (i < nnz)
        atomicAdd(&g_wt[(size_t)rows[i] * K_DIM + cols[i]], __float2half(sw[i]));
}

// ---------------------------------------------------------------------------
// GEMM: C[M,N] = A @ W'^T + bias
//   mma.sync m16n8k16 f16 (f32 acc), CTA 128x128, 4 warps 2x2 (64x64 each),
//   BK=64, 3-stage cp.async + mbarrier pipeline (no block barriers), 2 CTAs/SM.
// ---------------------------------------------------------------------------
__global__ __launch_bounds__(NTHREADS, 2)
void gemm_f16_kernel(const float* __restrict__ bias,
                     float* __restrict__ C) {
    extern __shared__ char smem[];
    const uint32_t sb = smem_u32(smem);

    const int tid  = threadIdx.x;
    const int wid  = tid >> 5;
    const int lane = tid & 31;
    const int lr   = lane >> 2;
    const int lq   = lane & 3;

    const int warpM = (wid >> 1) * 64;   // 0 or 64
    const int warpN = (wid & 1) * 64;    // 0 or 64

    const int bm = blockIdx.y * BM;
    const int bn = blockIdx.x * BN;

    const __half* Ab = g_x + (size_t)bm * K_DIM;
    const __half* Bb = g_wt + (size_t)bn * K_DIM;

#define FULL(s)  (sb + MB_OFF + (s) * 16)
#define EMPTY(s) (sb + MB_OFF + (s) * 16 + 8)

    if (tid == 0) {
#pragma unroll
        for (int q = 0; q < STAGES; q++) {
            MBAR_INIT(FULL(q), NTHREADS);   // one cp-completion arrive/thread
            MBAR_INIT(EMPTY(q), NTHREADS);  // one reader arrive/thread
        }
    }
    __syncthreads();   // only block barrier in the kernel

    // ldmatrix lane->address mapping
    const int aRow  = warpM + (lane & 15);
    const int aCSel = lane >> 4;
    const int bRow  = warpN + (lane & 7) + ((lane >> 4) << 3);
    const int bCSel = (lane >> 3) & 1;

    // tile loader: 16B chunk (row r, chunk c 0..7) -> smem r*128 + ((c^(r&7))*16)
#define LOAD_TILE(t, s)                                                         \
    {                                                                           \
        const uint32_t ab = sb + (s) * A_STAGE_BYTES;                           \
        _Pragma("unroll")                                                       \
        for (int j = 0; j < 8; j++) {                                           \
            int i = tid + j * NTHREADS;          /* 0..1023 */                  \
            int r = i >> 3, c = i & 7;                                          \
            uint32_t dst = ab + (uint32_t)(r * 128 + ((c ^ (r & 7)) << 4));     \
            CP_ASYNC16(dst, Ab + (size_t)r * K_DIM + (t) * BK + c * 8);         \
        }                                                                       \
        const uint32_t bb = sb + STAGES * A_STAGE_BYTES + (s) * B_STAGE_BYTES;  \
        _Pragma("unroll")                                                       \
        for (int j = 0; j < 8; j++) {                                           \
            int i = tid + j * NTHREADS;          /* 0..1023 */                  \
            int r = i >> 3, c = i & 7;                                          \
            uint32_t dst = bb + (uint32_t)(r * 128 + ((c ^ (r & 7)) << 4));     \
            CP_ASYNC16(dst, Bb + (size_t)r * K_DIM + (t) * BK + c * 8);         \
        }                                                                       \
    }

    // prologue: tiles 0,1 into stages 0,1 (full-arrive fires on completion)
    LOAD_TILE(0, 0);
    CP_MBAR_ARRIVE(FULL(0));
    LOAD_TILE(1, 1);
    CP_MBAR_ARRIVE(FULL(1));

    float acc[4][8][4];
#pragma unroll
    for (int i = 0; i < 4; i++)
#pragma unroll
        for (int j = 0; j < 8; j++)
#pragma unroll
            for (int q = 0; q < 4; q++) acc[i][j][q] = 0.0f;

    uint32_t fph = 0, eph = 0;   // per-stage phase bits
    int s = 0;                   // stage of tile t
    int sp = 2;                  // stage for prefetch (t+2)
    for (int t = 0; t < NKT; t++) {
        // producer: refill stage sp with tile t+2
        if (t + 2 < NKT) {
            if (t >= 1) {        // sp was last read as tile t-1 (same stage)
                MBAR_WAIT(EMPTY(sp), (eph >> sp) & 1);
                eph ^= (1u << sp);
            }
            LOAD_TILE(t + 2, sp);
            CP_MBAR_ARRIVE(FULL(sp));
        }

        // consumer: wait for tile t from ALL threads' cp.asyncs
        MBAR_WAIT(FULL(s), (fph >> s) & 1);
        fph ^= (1u << s);

        const uint32_t abase = sb + s * A_STAGE_BYTES;
        const uint32_t bbase = sb + STAGES * A_STAGE_BYTES + s * B_STAGE_BYTES;

#pragma unroll
        for (int kk = 0; kk < 4; kk++) {
            uint32_t ua[4][4], ub[4][4];
#pragma unroll
            for (int mt = 0; mt < 4; mt++) {
                const int r = aRow + mt * 16;
                const int c = 2 * kk + aCSel;
                const uint32_t addr =
                    abase + (uint32_t)(r * 128 + ((c ^ (r & 7)) << 4));
                LDSM_X4(ua[mt][0], ua[mt][1], ua[mt][2], ua[mt][3], addr);
            }
#pragma unroll
            for (int ntp = 0; ntp < 4; ntp++) {
                const int n = bRow + ntp * 16;
                const int c = 2 * kk + bCSel;
                const uint32_t addr =
                    bbase + (uint32_t)(n * 128 + ((c ^ (n & 7)) << 4));
                LDSM_X4(ub[ntp][0], ub[ntp][1], ub[ntp][2], ub[ntp][3], addr);
            }
#pragma unroll
            for (int mt = 0; mt < 4; mt++)
#pragma unroll
                for (int nt = 0; nt < 8; nt++) {
                    const uint32_t b0 = (nt & 1) ? ub[nt >> 1][2] : ub[nt >> 1][0];
                    const uint32_t b1 = (nt & 1) ? ub[nt >> 1][3] : ub[nt >> 1][1];
                    mma_f16(acc[mt][nt][0], acc[mt][nt][1],
                            acc[mt][nt][2], acc[mt][nt][3],
                            ua[mt][0], ua[mt][1], ua[mt][2], ua[mt][3],
                            b0, b1);
                }
        }

        // reader done with stage s (MMAs issued => LDSMs completed)
        MBAR_ARRIVE(EMPTY(s));

        s = (s == 2) ? 0 : s + 1;
        sp = (sp == 2) ? 0 : sp + 1;
    }

    // Epilogue: bias + store
#pragma unroll
    for (int nt = 0; nt < 8; nt++) {
        const int col = bn + warpN + nt * 8 + lq * 2;
        const float bv0 = bias[col];
        const float bv1 = bias[col + 1];
#pragma unroll
        for (int mt = 0; mt < 4; mt++) {
            const int r0 = bm + warpM + mt * 16 + lr;
            float2 v0, v1;
            v0.x = acc[mt][nt][0] + bv0;
            v0.y = acc[mt][nt][1] + bv1;
            v1.x = acc[mt][nt][2] + bv0;
            v1.y = acc[mt][nt][3] + bv1;
            *reinterpret_cast<float2*>(&C[(size_t)r0 * N_DIM + col]) = v0;
            *reinterpret_cast<float2*>(&C[(size_t)(r0 + 8) * N_DIM + col]) = v1;
        }
    }
}

// ---------------------------------------------------------------------------
// Launch
// ---------------------------------------------------------------------------
extern "C" void kernel_launch(void* const* d_in, const int* in_sizes, int n_in,
                              void* d_out, int out_size) {
    const float* x    = (const float*)d_in[0];
    const float* w    = (const float*)d_in[1];
    const float* bias = (const float*)d_in[2];
    const float* sw   = (const float*)d_in[3];
    const int*   idx  = (const int*)d_in[4];
    float*       out  = (float*)d_out;
    const int nnz = in_sizes[3];

    // 1) W' = half(W)
    convert_w_kernel<<<(N_DIM * K_DIM / 8) / 256, 256>>>(
        reinterpret_cast<const float4*>(w));
    // 2) W' += scatter(sw)  (half atomics)
    scatter_add_kernel<<<(nnz + 255) / 256, 256>>>(sw, idx, idx + nnz, nnz);
    // 3) x' = half(x)
    convert_x_kernel<<<(int)(((size_t)M_DIM * K_DIM / 8) / 256), 256>>>(
        reinterpret_cast<const float4*>(x));

    // 4) GEMM
    cudaFuncSetAttribute(gemm_f16_kernel,
                         cudaFuncAttributeMaxDynamicSharedMemorySize, SMEM_TOTAL);
    dim3 grid(N_DIM / BN, M_DIM / BM);   // (32, 64)
    gemm_f16_kernel<<<grid, NTHREADS, SMEM_TOTAL>>>(bias, out);
}